// round 1
// baseline (speedup 1.0000x reference)
#include <cuda_runtime.h>

#define Nn 200000
#define Ee 3200000
#define IND 165
#define HID 64

// Scratch (no cudaMalloc allowed)
__device__ float g_h0[Nn * HID];
__device__ float g_h1[Nn * HID];
__device__ float g_aggr[Nn * HID];
__device__ float g_deg[Nn];

// ---------------- proj: h0 = relu(x @ W_proj + b) ----------------
__global__ __launch_bounds__(256) void proj_kernel(
    const float* __restrict__ x, const float* __restrict__ Wp,
    const float* __restrict__ bp, float* __restrict__ out)
{
    __shared__ float Ws[IND * HID];   // 42.2 KB
    __shared__ float xs[4][IND];
    for (int i = threadIdx.x; i < IND * HID; i += blockDim.x) Ws[i] = Wp[i];
    const int j = threadIdx.x & 63;
    const int r = threadIdx.x >> 6;
    const float bj = bp[j];
    const int tiles = (Nn + 3) / 4;
    for (int tile = blockIdx.x; tile < tiles; tile += gridDim.x) {
        const int n0 = tile * 4;
        __syncthreads();
        for (int i = threadIdx.x; i < 4 * IND; i += blockDim.x) {
            int rr = i / IND, c = i - rr * IND;
            int n = n0 + rr;
            xs[rr][c] = (n < Nn) ? x[(long long)n * IND + c] : 0.0f;
        }
        __syncthreads();
        const int n = n0 + r;
        if (n < Nn) {
            float acc = bj;
            #pragma unroll 5
            for (int k = 0; k < IND; k++)
                acc = fmaf(xs[r][k], Ws[k * HID + j], acc);
            out[(long long)n * HID + j] = fmaxf(acc, 0.0f);
        }
    }
}

// ---------------- degree count + inverse ----------------
__global__ __launch_bounds__(256) void deg_kernel(const int* __restrict__ dst)
{
    int e = blockIdx.x * blockDim.x + threadIdx.x;
    if (e < Ee) atomicAdd(&g_deg[dst[e]], 1.0f);
}

__global__ __launch_bounds__(256) void invdeg_kernel()
{
    int n = blockIdx.x * blockDim.x + threadIdx.x;
    if (n < Nn) g_deg[n] = 1.0f / fmaxf(g_deg[n], 1.0f);
}

// ---------------- edge scatter: aggr[dst] += h[src] ----------------
// 16 threads per edge, each thread handles one float4 (coalesced 256B gather
// per edge, vectorized red.global.add.v4.f32 scatter — no return trip).
__global__ __launch_bounds__(256) void scatter_kernel(
    const int* __restrict__ src, const int* __restrict__ dst,
    const float* __restrict__ h, float* __restrict__ aggr)
{
    long long t = (long long)blockIdx.x * blockDim.x + threadIdx.x;
    long long e = t >> 4;
    if (e >= Ee) return;
    const int q = (int)(t & 15);
    const int s = src[e];
    const int d = dst[e];
    const float4 v = *reinterpret_cast<const float4*>(h + (long long)s * HID + q * 4);
    float* p = aggr + (long long)d * HID + q * 4;
    asm volatile("red.global.add.v4.f32 [%0], {%1, %2, %3, %4};"
                 :: "l"(p), "f"(v.x), "f"(v.y), "f"(v.z), "f"(v.w)
                 : "memory");
}

// ------- SAGE: out = relu((aggr*invdeg) @ W_l + b_l + h @ W_r) -------
__global__ __launch_bounds__(256) void sage_kernel(
    const float* __restrict__ h, const float* __restrict__ aggr,
    const float* __restrict__ Wl, const float* __restrict__ bl,
    const float* __restrict__ Wr, float* __restrict__ out)
{
    __shared__ float sWl[HID * HID];  // 16 KB
    __shared__ float sWr[HID * HID];  // 16 KB
    __shared__ float as[4][HID];
    __shared__ float hs[4][HID];
    for (int i = threadIdx.x; i < HID * HID; i += blockDim.x) {
        sWl[i] = Wl[i];
        sWr[i] = Wr[i];
    }
    const int j = threadIdx.x & 63;
    const int r = threadIdx.x >> 6;
    const float bj = bl[j];
    const int tiles = (Nn + 3) / 4;
    for (int tile = blockIdx.x; tile < tiles; tile += gridDim.x) {
        const int n0 = tile * 4;
        __syncthreads();
        {
            int rr = threadIdx.x >> 6;   // 4 rows, 64 cols: exactly 256 threads
            int c = threadIdx.x & 63;
            int n = n0 + rr;
            if (n < Nn) {
                float inv = g_deg[n];
                as[rr][c] = aggr[(long long)n * HID + c] * inv;
                hs[rr][c] = h[(long long)n * HID + c];
            } else {
                as[rr][c] = 0.0f;
                hs[rr][c] = 0.0f;
            }
        }
        __syncthreads();
        const int n = n0 + r;
        if (n < Nn) {
            float acc = bj;
            #pragma unroll 8
            for (int k = 0; k < HID; k++) {
                acc = fmaf(as[r][k], sWl[k * HID + j], acc);
                acc = fmaf(hs[r][k], sWr[k * HID + j], acc);
            }
            out[(long long)n * HID + j] = fmaxf(acc, 0.0f);
        }
    }
}

// ---------------- classifier: out[n] = h[n] . W_cls + b ----------------
__global__ __launch_bounds__(256) void cls_kernel(
    const float* __restrict__ h, const float* __restrict__ Wc,
    const float* __restrict__ bc, float* __restrict__ out)
{
    long long t = (long long)blockIdx.x * blockDim.x + threadIdx.x;
    long long n = t >> 5;
    if (n >= Nn) return;
    const int lane = (int)(t & 31);
    const float* hp = h + n * HID;
    float acc = fmaf(hp[lane], Wc[lane], hp[32 + lane] * Wc[32 + lane]);
    #pragma unroll
    for (int o = 16; o; o >>= 1) acc += __shfl_xor_sync(0xffffffffu, acc, o);
    if (lane == 0) out[n] = acc + bc[0];
}

extern "C" void kernel_launch(void* const* d_in, const int* in_sizes, int n_in,
                              void* d_out, int out_size)
{
    const float* x   = (const float*)d_in[0];
    const int*   ei  = (const int*)d_in[1];
    const float* Wp  = (const float*)d_in[2];
    const float* bp  = (const float*)d_in[3];
    const float* W1l = (const float*)d_in[4];
    const float* b1l = (const float*)d_in[5];
    const float* W1r = (const float*)d_in[6];
    const float* W2l = (const float*)d_in[7];
    const float* b2l = (const float*)d_in[8];
    const float* W2r = (const float*)d_in[9];
    const float* Wc  = (const float*)d_in[10];
    const float* bc  = (const float*)d_in[11];
    float* out = (float*)d_out;

    const int* src = ei;
    const int* dst = ei + Ee;

    float *h0, *h1, *aggr, *deg;
    cudaGetSymbolAddress((void**)&h0, g_h0);
    cudaGetSymbolAddress((void**)&h1, g_h1);
    cudaGetSymbolAddress((void**)&aggr, g_aggr);
    cudaGetSymbolAddress((void**)&deg, g_deg);

    // zero degree + aggregation buffers
    cudaMemsetAsync(deg, 0, Nn * sizeof(float));
    cudaMemsetAsync(aggr, 0, (size_t)Nn * HID * sizeof(float));

    // h0 = relu(x @ Wp + bp)
    proj_kernel<<<592, 256>>>(x, Wp, bp, h0);

    // degree + inverse
    deg_kernel<<<(Ee + 255) / 256, 256>>>(dst);
    invdeg_kernel<<<(Nn + 255) / 256, 256>>>();

    // ---- layer 1 ----
    {
        long long threads = (long long)Ee * 16;
        scatter_kernel<<<(unsigned)((threads + 255) / 256), 256>>>(src, dst, h0, aggr);
        sage_kernel<<<888, 256>>>(h0, aggr, W1l, b1l, W1r, h1);
    }

    // ---- layer 2 ----
    cudaMemsetAsync(aggr, 0, (size_t)Nn * HID * sizeof(float));
    {
        long long threads = (long long)Ee * 16;
        scatter_kernel<<<(unsigned)((threads + 255) / 256), 256>>>(src, dst, h1, aggr);
        sage_kernel<<<888, 256>>>(h1, aggr, W2l, b2l, W2r, h0);  // h0 reused as h2
    }

    // classifier
    {
        long long threads = (long long)Nn * 32;
        cls_kernel<<<(unsigned)((threads + 255) / 256), 256>>>(h0, Wc, bc, out);
    }
}

// round 2
// speedup vs baseline: 1.7182x; 1.7182x over previous
#include <cuda_runtime.h>

#define Nn 200000
#define Ee 3200000
#define IND 165
#define HID 64
#define NB1K 196   // ceil(Nn/1024)

// ---- scratch (no cudaMalloc allowed) ----
__device__ float g_h0[Nn * HID];
__device__ float g_h1[Nn * HID];
__device__ float g_aggr[Nn * HID];
__device__ int   g_degi[Nn];
__device__ int   g_off[Nn];
__device__ int   g_cur[Nn];
__device__ int   g_csr[Ee];
__device__ int   g_bsum[256];
__device__ int   g_bscan[256];

// =================== degree histogram (int) ===================
__global__ __launch_bounds__(256) void deg_kernel(const int* __restrict__ dst, int* __restrict__ degi)
{
    int e = blockIdx.x * blockDim.x + threadIdx.x;
    if (e < Ee) atomicAdd(&degi[dst[e]], 1);
}

// =================== 2-level exclusive scan ===================
__global__ __launch_bounds__(256) void scan1(const int* __restrict__ degi, int* __restrict__ bsum)
{
    __shared__ int s[256];
    int base = blockIdx.x * 1024 + threadIdx.x * 4;
    int sum = 0;
    #pragma unroll
    for (int i = 0; i < 4; i++) { int n = base + i; if (n < Nn) sum += degi[n]; }
    s[threadIdx.x] = sum; __syncthreads();
    for (int o = 128; o; o >>= 1) {
        if (threadIdx.x < o) s[threadIdx.x] += s[threadIdx.x + o];
        __syncthreads();
    }
    if (threadIdx.x == 0) bsum[blockIdx.x] = s[0];
}

__global__ __launch_bounds__(256) void scan2(const int* __restrict__ bsum, int* __restrict__ bscan)
{
    __shared__ int s[256];
    int v = (threadIdx.x < NB1K) ? bsum[threadIdx.x] : 0;
    s[threadIdx.x] = v; __syncthreads();
    for (int o = 1; o < 256; o <<= 1) {
        int t = (threadIdx.x >= o) ? s[threadIdx.x - o] : 0;
        __syncthreads();
        s[threadIdx.x] += t;
        __syncthreads();
    }
    if (threadIdx.x < NB1K) bscan[threadIdx.x] = s[threadIdx.x] - v;  // exclusive
}

__global__ __launch_bounds__(256) void scan3(const int* __restrict__ degi, const int* __restrict__ bscan,
                                             int* __restrict__ off, int* __restrict__ cur)
{
    __shared__ int s[256];
    int tid = threadIdx.x;
    int base = blockIdx.x * 1024 + tid * 4;
    int d[4]; int sum = 0;
    #pragma unroll
    for (int i = 0; i < 4; i++) { int n = base + i; d[i] = (n < Nn) ? degi[n] : 0; sum += d[i]; }
    s[tid] = sum; __syncthreads();
    for (int o = 1; o < 256; o <<= 1) {
        int t = (tid >= o) ? s[tid - o] : 0;
        __syncthreads();
        s[tid] += t;
        __syncthreads();
    }
    int ex = s[tid] - sum + bscan[blockIdx.x];
    #pragma unroll
    for (int i = 0; i < 4; i++) {
        int n = base + i;
        if (n < Nn) { off[n] = ex; cur[n] = ex; ex += d[i]; }
    }
}

__global__ __launch_bounds__(256) void place_kernel(const int* __restrict__ src, const int* __restrict__ dst,
                                                    int* __restrict__ cur, int* __restrict__ csr)
{
    int e = blockIdx.x * blockDim.x + threadIdx.x;
    if (e < Ee) {
        int p = atomicAdd(&cur[dst[e]], 1);
        csr[p] = src[e];
    }
}

// =================== gather-mean (warp per node) ===================
__global__ __launch_bounds__(256) void gather_mean(
    const int* __restrict__ csr, const int* __restrict__ off, const int* __restrict__ degi,
    const float* __restrict__ h, float* __restrict__ aggr)
{
    long long t = (long long)blockIdx.x * blockDim.x + threadIdx.x;
    int node = (int)(t >> 5);
    if (node >= Nn) return;
    int lane = threadIdx.x & 31;
    int half = lane >> 4;      // 0/1 : alternates edges
    int q = lane & 15;         // float4 slot (cols q*4..q*4+3)
    int beg = off[node];
    int d = degi[node];
    float4 acc = make_float4(0.f, 0.f, 0.f, 0.f);
    for (int i = half; i < d; i += 2) {
        int s = __ldg(&csr[beg + i]);
        float4 v = *reinterpret_cast<const float4*>(h + (size_t)s * HID + q * 4);
        acc.x += v.x; acc.y += v.y; acc.z += v.z; acc.w += v.w;
    }
    acc.x += __shfl_xor_sync(0xffffffffu, acc.x, 16);
    acc.y += __shfl_xor_sync(0xffffffffu, acc.y, 16);
    acc.z += __shfl_xor_sync(0xffffffffu, acc.z, 16);
    acc.w += __shfl_xor_sync(0xffffffffu, acc.w, 16);
    if (half == 0) {
        float inv = 1.0f / fmaxf((float)d, 1.0f);
        acc.x *= inv; acc.y *= inv; acc.z *= inv; acc.w *= inv;
        *reinterpret_cast<float4*>(aggr + (size_t)node * HID + q * 4) = acc;
    }
}

// =================== proj GEMM: h0 = relu(x @ Wp + bp) ===================
// register-tiled: 32-node tile, thread owns 2 nodes x 4 cols
#define XS_STRIDE 168
#define PROJ_SMEM ((IND * HID + 32 * XS_STRIDE) * 4)

__global__ __launch_bounds__(256) void proj_gemm(
    const float* __restrict__ x, const float* __restrict__ Wp,
    const float* __restrict__ bp, float* __restrict__ out)
{
    extern __shared__ float sm[];
    float* Ws = sm;                  // [IND][64]
    float* Xs = sm + IND * HID;      // [32][XS_STRIDE]
    const int t = threadIdx.x;
    for (int i = t; i < IND * HID; i += 256) Ws[i] = Wp[i];
    const int cg = t & 15;           // col group
    const int ng = t >> 4;           // node group (2 nodes)
    float b0 = bp[cg * 4 + 0], b1 = bp[cg * 4 + 1], b2 = bp[cg * 4 + 2], b3 = bp[cg * 4 + 3];
    const int ntiles = (Nn + 31) / 32;
    for (int tile = blockIdx.x; tile < ntiles; tile += gridDim.x) {
        const int n0 = tile * 32;
        __syncthreads();
        // load X tile (coalesced: linear index over 32*IND elems)
        for (int i = t; i < 32 * IND; i += 256) {
            int node = i / IND;
            int c = i - node * IND;
            int n = n0 + node;
            Xs[node * XS_STRIDE + c] = (n < Nn) ? x[(size_t)n * IND + c] : 0.0f;
        }
        __syncthreads();
        float acc[2][4];
        acc[0][0] = b0; acc[0][1] = b1; acc[0][2] = b2; acc[0][3] = b3;
        acc[1][0] = b0; acc[1][1] = b1; acc[1][2] = b2; acc[1][3] = b3;
        const float* xr0 = Xs + (ng * 2 + 0) * XS_STRIDE;
        const float* xr1 = Xs + (ng * 2 + 1) * XS_STRIDE;
        #pragma unroll 4
        for (int k4 = 0; k4 < IND / 4; k4++) {   // 41 iters
            float4 a0 = *reinterpret_cast<const float4*>(xr0 + k4 * 4);
            float4 a1 = *reinterpret_cast<const float4*>(xr1 + k4 * 4);
            #pragma unroll
            for (int kk = 0; kk < 4; kk++) {
                float4 w = *reinterpret_cast<const float4*>(Ws + (k4 * 4 + kk) * HID + cg * 4);
                float av0 = (kk == 0) ? a0.x : (kk == 1) ? a0.y : (kk == 2) ? a0.z : a0.w;
                float av1 = (kk == 0) ? a1.x : (kk == 1) ? a1.y : (kk == 2) ? a1.z : a1.w;
                acc[0][0] = fmaf(av0, w.x, acc[0][0]);
                acc[0][1] = fmaf(av0, w.y, acc[0][1]);
                acc[0][2] = fmaf(av0, w.z, acc[0][2]);
                acc[0][3] = fmaf(av0, w.w, acc[0][3]);
                acc[1][0] = fmaf(av1, w.x, acc[1][0]);
                acc[1][1] = fmaf(av1, w.y, acc[1][1]);
                acc[1][2] = fmaf(av1, w.z, acc[1][2]);
                acc[1][3] = fmaf(av1, w.w, acc[1][3]);
            }
        }
        {   // tail k = 164
            const int k = IND - 1;
            float4 w = *reinterpret_cast<const float4*>(Ws + k * HID + cg * 4);
            float av0 = xr0[k], av1 = xr1[k];
            acc[0][0] = fmaf(av0, w.x, acc[0][0]);
            acc[0][1] = fmaf(av0, w.y, acc[0][1]);
            acc[0][2] = fmaf(av0, w.z, acc[0][2]);
            acc[0][3] = fmaf(av0, w.w, acc[0][3]);
            acc[1][0] = fmaf(av1, w.x, acc[1][0]);
            acc[1][1] = fmaf(av1, w.y, acc[1][1]);
            acc[1][2] = fmaf(av1, w.z, acc[1][2]);
            acc[1][3] = fmaf(av1, w.w, acc[1][3]);
        }
        #pragma unroll
        for (int i = 0; i < 2; i++) {
            int n = n0 + ng * 2 + i;
            if (n < Nn) {
                float4 o;
                o.x = fmaxf(acc[i][0], 0.f);
                o.y = fmaxf(acc[i][1], 0.f);
                o.z = fmaxf(acc[i][2], 0.f);
                o.w = fmaxf(acc[i][3], 0.f);
                *reinterpret_cast<float4*>(out + (size_t)n * HID + cg * 4) = o;
            }
        }
    }
}

// ====== SAGE GEMM: out = relu([aggr | h] @ [Wl ; Wr] + bl) ======
// aggr is pre-normalized (mean). K = 128. 64-node tile, thread owns 4 nodes x 4 cols.
#define AS_STRIDE 132
#define SAGE_SMEM ((128 * HID + 64 * AS_STRIDE) * 4)

__global__ __launch_bounds__(256) void sage_gemm(
    const float* __restrict__ h, const float* __restrict__ aggr,
    const float* __restrict__ Wl, const float* __restrict__ bl,
    const float* __restrict__ Wr, float* __restrict__ out)
{
    extern __shared__ float sm[];
    float* Ws = sm;                  // [128][64]: rows 0-63 Wl, 64-127 Wr
    float* As = sm + 128 * HID;      // [64][AS_STRIDE]
    const int t = threadIdx.x;
    for (int i = t; i < HID * HID; i += 256) {
        Ws[i] = Wl[i];
        Ws[HID * HID + i] = Wr[i];
    }
    const int cg = t & 15;
    const int ng = t >> 4;           // 16 groups x 4 nodes
    float b0 = bl[cg * 4 + 0], b1 = bl[cg * 4 + 1], b2 = bl[cg * 4 + 2], b3 = bl[cg * 4 + 3];
    const int ntiles = (Nn + 63) / 64;
    for (int tile = blockIdx.x; tile < ntiles; tile += gridDim.x) {
        const int n0 = tile * 64;
        __syncthreads();
        // load A tile: node row = [aggr(64) | h(64)]
        for (int i = t; i < 64 * 32; i += 256) {
            int node = i >> 5;
            int p = i & 31;
            int n = n0 + node;
            float4 v;
            if (n < Nn)
                v = (p < 16) ? *reinterpret_cast<const float4*>(aggr + (size_t)n * HID + p * 4)
                             : *reinterpret_cast<const float4*>(h + (size_t)n * HID + (p - 16) * 4);
            else
                v = make_float4(0.f, 0.f, 0.f, 0.f);
            *reinterpret_cast<float4*>(As + node * AS_STRIDE + p * 4) = v;
        }
        __syncthreads();
        float acc[4][4];
        #pragma unroll
        for (int i = 0; i < 4; i++) { acc[i][0] = b0; acc[i][1] = b1; acc[i][2] = b2; acc[i][3] = b3; }
        #pragma unroll 2
        for (int k4 = 0; k4 < 32; k4++) {
            float4 a[4];
            #pragma unroll
            for (int i = 0; i < 4; i++)
                a[i] = *reinterpret_cast<const float4*>(As + (ng * 4 + i) * AS_STRIDE + k4 * 4);
            #pragma unroll
            for (int kk = 0; kk < 4; kk++) {
                float4 w = *reinterpret_cast<const float4*>(Ws + (k4 * 4 + kk) * HID + cg * 4);
                #pragma unroll
                for (int i = 0; i < 4; i++) {
                    float av = (kk == 0) ? a[i].x : (kk == 1) ? a[i].y : (kk == 2) ? a[i].z : a[i].w;
                    acc[i][0] = fmaf(av, w.x, acc[i][0]);
                    acc[i][1] = fmaf(av, w.y, acc[i][1]);
                    acc[i][2] = fmaf(av, w.z, acc[i][2]);
                    acc[i][3] = fmaf(av, w.w, acc[i][3]);
                }
            }
        }
        #pragma unroll
        for (int i = 0; i < 4; i++) {
            int n = n0 + ng * 4 + i;
            if (n < Nn) {
                float4 o;
                o.x = fmaxf(acc[i][0], 0.f);
                o.y = fmaxf(acc[i][1], 0.f);
                o.z = fmaxf(acc[i][2], 0.f);
                o.w = fmaxf(acc[i][3], 0.f);
                *reinterpret_cast<float4*>(out + (size_t)n * HID + cg * 4) = o;
            }
        }
    }
}

// =================== classifier ===================
__global__ __launch_bounds__(256) void cls_kernel(
    const float* __restrict__ h, const float* __restrict__ Wc,
    const float* __restrict__ bc, float* __restrict__ out)
{
    long long t = (long long)blockIdx.x * blockDim.x + threadIdx.x;
    long long n = t >> 5;
    if (n >= Nn) return;
    const int lane = (int)(t & 31);
    const float* hp = h + n * HID;
    float acc = fmaf(hp[lane], Wc[lane], hp[32 + lane] * Wc[32 + lane]);
    #pragma unroll
    for (int o = 16; o; o >>= 1) acc += __shfl_xor_sync(0xffffffffu, acc, o);
    if (lane == 0) out[n] = acc + bc[0];
}

extern "C" void kernel_launch(void* const* d_in, const int* in_sizes, int n_in,
                              void* d_out, int out_size)
{
    const float* x   = (const float*)d_in[0];
    const int*   ei  = (const int*)d_in[1];
    const float* Wp  = (const float*)d_in[2];
    const float* bp  = (const float*)d_in[3];
    const float* W1l = (const float*)d_in[4];
    const float* b1l = (const float*)d_in[5];
    const float* W1r = (const float*)d_in[6];
    const float* W2l = (const float*)d_in[7];
    const float* b2l = (const float*)d_in[8];
    const float* W2r = (const float*)d_in[9];
    const float* Wc  = (const float*)d_in[10];
    const float* bc  = (const float*)d_in[11];
    float* out = (float*)d_out;

    const int* src = ei;
    const int* dst = ei + Ee;

    float *h0, *h1, *aggr;
    int *degi, *off, *cur, *csr, *bsum, *bscan;
    cudaGetSymbolAddress((void**)&h0, g_h0);
    cudaGetSymbolAddress((void**)&h1, g_h1);
    cudaGetSymbolAddress((void**)&aggr, g_aggr);
    cudaGetSymbolAddress((void**)&degi, g_degi);
    cudaGetSymbolAddress((void**)&off, g_off);
    cudaGetSymbolAddress((void**)&cur, g_cur);
    cudaGetSymbolAddress((void**)&csr, g_csr);
    cudaGetSymbolAddress((void**)&bsum, g_bsum);
    cudaGetSymbolAddress((void**)&bscan, g_bscan);

    static bool attr_done = false;
    if (!attr_done) {
        cudaFuncSetAttribute(proj_gemm, cudaFuncAttributeMaxDynamicSharedMemorySize, PROJ_SMEM);
        cudaFuncSetAttribute(sage_gemm, cudaFuncAttributeMaxDynamicSharedMemorySize, SAGE_SMEM);
        attr_done = true;
    }

    // ---- CSR build ----
    cudaMemsetAsync(degi, 0, Nn * sizeof(int));
    deg_kernel<<<(Ee + 255) / 256, 256>>>(dst, degi);
    scan1<<<NB1K, 256>>>(degi, bsum);
    scan2<<<1, 256>>>(bsum, bscan);
    scan3<<<NB1K, 256>>>(degi, bscan, off, cur);
    place_kernel<<<(Ee + 255) / 256, 256>>>(src, dst, cur, csr);

    // ---- proj ----
    proj_gemm<<<444, 256, PROJ_SMEM>>>(x, Wp, bp, h0);

    // ---- layer 1 ----
    gather_mean<<<(Nn * 32 + 255) / 256, 256>>>(csr, off, degi, h0, aggr);
    sage_gemm<<<444, 256, SAGE_SMEM>>>(h0, aggr, W1l, b1l, W1r, h1);

    // ---- layer 2 ----
    gather_mean<<<(Nn * 32 + 255) / 256, 256>>>(csr, off, degi, h1, aggr);
    sage_gemm<<<444, 256, SAGE_SMEM>>>(h1, aggr, W2l, b2l, W2r, h0);

    // ---- classifier ----
    cls_kernel<<<(Nn * 32 + 255) / 256, 256>>>(h0, Wc, bc, out);
}

// round 3
// speedup vs baseline: 2.5588x; 1.4892x over previous
#include <cuda_runtime.h>

#define Nn 200000
#define Ee 3200000
#define IND 165
#define HID 64
#define NB1K 196   // ceil(Nn/1024)

// ---- scratch (no cudaMalloc allowed) ----
__device__ float g_h0[Nn * HID];
__device__ float g_h1[Nn * HID];
__device__ float g_aggr[Nn * HID];
__device__ int   g_degi[Nn];
__device__ int   g_off[Nn];
__device__ int   g_cur[Nn];
__device__ int   g_csr[Ee];
__device__ int   g_bsum[256];
__device__ int   g_bscan[256];

// =================== degree histogram (int) ===================
__global__ __launch_bounds__(256) void deg_kernel(const int* __restrict__ dst, int* __restrict__ degi)
{
    int e = blockIdx.x * blockDim.x + threadIdx.x;
    if (e < Ee) atomicAdd(&degi[dst[e]], 1);
}

// =================== 2-level exclusive scan ===================
__global__ __launch_bounds__(256) void scan1(const int* __restrict__ degi, int* __restrict__ bsum)
{
    __shared__ int s[256];
    int base = blockIdx.x * 1024 + threadIdx.x * 4;
    int sum = 0;
    #pragma unroll
    for (int i = 0; i < 4; i++) { int n = base + i; if (n < Nn) sum += degi[n]; }
    s[threadIdx.x] = sum; __syncthreads();
    for (int o = 128; o; o >>= 1) {
        if (threadIdx.x < o) s[threadIdx.x] += s[threadIdx.x + o];
        __syncthreads();
    }
    if (threadIdx.x == 0) bsum[blockIdx.x] = s[0];
}

__global__ __launch_bounds__(256) void scan2(const int* __restrict__ bsum, int* __restrict__ bscan)
{
    __shared__ int s[256];
    int v = (threadIdx.x < NB1K) ? bsum[threadIdx.x] : 0;
    s[threadIdx.x] = v; __syncthreads();
    for (int o = 1; o < 256; o <<= 1) {
        int t = (threadIdx.x >= o) ? s[threadIdx.x - o] : 0;
        __syncthreads();
        s[threadIdx.x] += t;
        __syncthreads();
    }
    if (threadIdx.x < NB1K) bscan[threadIdx.x] = s[threadIdx.x] - v;  // exclusive
}

__global__ __launch_bounds__(256) void scan3(const int* __restrict__ degi, const int* __restrict__ bscan,
                                             int* __restrict__ off, int* __restrict__ cur)
{
    __shared__ int s[256];
    int tid = threadIdx.x;
    int base = blockIdx.x * 1024 + tid * 4;
    int d[4]; int sum = 0;
    #pragma unroll
    for (int i = 0; i < 4; i++) { int n = base + i; d[i] = (n < Nn) ? degi[n] : 0; sum += d[i]; }
    s[tid] = sum; __syncthreads();
    for (int o = 1; o < 256; o <<= 1) {
        int t = (tid >= o) ? s[tid - o] : 0;
        __syncthreads();
        s[tid] += t;
        __syncthreads();
    }
    int ex = s[tid] - sum + bscan[blockIdx.x];
    #pragma unroll
    for (int i = 0; i < 4; i++) {
        int n = base + i;
        if (n < Nn) { off[n] = ex; cur[n] = ex; ex += d[i]; }
    }
}

__global__ __launch_bounds__(256) void place_kernel(const int* __restrict__ src, const int* __restrict__ dst,
                                                    int* __restrict__ cur, int* __restrict__ csr)
{
    int e = blockIdx.x * blockDim.x + threadIdx.x;
    if (e < Ee) {
        int p = atomicAdd(&cur[dst[e]], 1);
        csr[p] = src[e];
    }
}

// =================== gather-mean (warp per node, MLP-unrolled) ===================
__global__ __launch_bounds__(256) void gather_mean(
    const int* __restrict__ csr, const int* __restrict__ off, const int* __restrict__ degi,
    const float* __restrict__ h, float* __restrict__ aggr)
{
    long long t = (long long)blockIdx.x * blockDim.x + threadIdx.x;
    int node = (int)(t >> 5);
    if (node >= Nn) return;
    int lane = threadIdx.x & 31;
    int half = lane >> 4;      // 0/1 : alternates edges
    int q = lane & 15;         // float4 slot (cols q*4..q*4+3)
    const int beg = off[node];
    const int d = degi[node];
    const int* cp = csr + beg;
    float4 acc = make_float4(0.f, 0.f, 0.f, 0.f);
    int i = half;
    // 4 edges in flight per half (batched index loads, then 4 independent gathers)
    for (; i + 6 < d; i += 8) {
        int s0 = __ldg(&cp[i]);
        int s1 = __ldg(&cp[i + 2]);
        int s2 = __ldg(&cp[i + 4]);
        int s3 = __ldg(&cp[i + 6]);
        float4 v0 = *reinterpret_cast<const float4*>(h + (size_t)s0 * HID + q * 4);
        float4 v1 = *reinterpret_cast<const float4*>(h + (size_t)s1 * HID + q * 4);
        float4 v2 = *reinterpret_cast<const float4*>(h + (size_t)s2 * HID + q * 4);
        float4 v3 = *reinterpret_cast<const float4*>(h + (size_t)s3 * HID + q * 4);
        acc.x += (v0.x + v1.x) + (v2.x + v3.x);
        acc.y += (v0.y + v1.y) + (v2.y + v3.y);
        acc.z += (v0.z + v1.z) + (v2.z + v3.z);
        acc.w += (v0.w + v1.w) + (v2.w + v3.w);
    }
    for (; i < d; i += 2) {
        int s = __ldg(&cp[i]);
        float4 v = *reinterpret_cast<const float4*>(h + (size_t)s * HID + q * 4);
        acc.x += v.x; acc.y += v.y; acc.z += v.z; acc.w += v.w;
    }
    acc.x += __shfl_xor_sync(0xffffffffu, acc.x, 16);
    acc.y += __shfl_xor_sync(0xffffffffu, acc.y, 16);
    acc.z += __shfl_xor_sync(0xffffffffu, acc.z, 16);
    acc.w += __shfl_xor_sync(0xffffffffu, acc.w, 16);
    if (half == 0) {
        float inv = 1.0f / fmaxf((float)d, 1.0f);
        acc.x *= inv; acc.y *= inv; acc.z *= inv; acc.w *= inv;
        *reinterpret_cast<float4*>(aggr + (size_t)node * HID + q * 4) = acc;
    }
}

// =================== proj GEMM: h0 = relu(x @ Wp + bp) ===================
#define XS_STRIDE 168
#define PROJ_SMEM ((IND * HID + 32 * XS_STRIDE) * 4)

__global__ __launch_bounds__(256) void proj_gemm(
    const float* __restrict__ x, const float* __restrict__ Wp,
    const float* __restrict__ bp, float* __restrict__ out)
{
    extern __shared__ float sm[];
    float* Ws = sm;                  // [IND][64]
    float* Xs = sm + IND * HID;      // [32][XS_STRIDE]
    const int t = threadIdx.x;
    for (int i = t; i < IND * HID; i += 256) Ws[i] = Wp[i];
    const int cg = t & 15;           // col group
    const int ng = t >> 4;           // node group (2 nodes)
    float b0 = bp[cg * 4 + 0], b1 = bp[cg * 4 + 1], b2 = bp[cg * 4 + 2], b3 = bp[cg * 4 + 3];
    const int ntiles = (Nn + 31) / 32;
    for (int tile = blockIdx.x; tile < ntiles; tile += gridDim.x) {
        const int n0 = tile * 32;
        __syncthreads();
        for (int i = t; i < 32 * IND; i += 256) {
            int node = i / IND;
            int c = i - node * IND;
            int n = n0 + node;
            Xs[node * XS_STRIDE + c] = (n < Nn) ? x[(size_t)n * IND + c] : 0.0f;
        }
        __syncthreads();
        float acc[2][4];
        acc[0][0] = b0; acc[0][1] = b1; acc[0][2] = b2; acc[0][3] = b3;
        acc[1][0] = b0; acc[1][1] = b1; acc[1][2] = b2; acc[1][3] = b3;
        const float* xr0 = Xs + (ng * 2 + 0) * XS_STRIDE;
        const float* xr1 = Xs + (ng * 2 + 1) * XS_STRIDE;
        #pragma unroll 4
        for (int k4 = 0; k4 < IND / 4; k4++) {   // 41 iters
            float4 a0 = *reinterpret_cast<const float4*>(xr0 + k4 * 4);
            float4 a1 = *reinterpret_cast<const float4*>(xr1 + k4 * 4);
            #pragma unroll
            for (int kk = 0; kk < 4; kk++) {
                float4 w = *reinterpret_cast<const float4*>(Ws + (k4 * 4 + kk) * HID + cg * 4);
                float av0 = (kk == 0) ? a0.x : (kk == 1) ? a0.y : (kk == 2) ? a0.z : a0.w;
                float av1 = (kk == 0) ? a1.x : (kk == 1) ? a1.y : (kk == 2) ? a1.z : a1.w;
                acc[0][0] = fmaf(av0, w.x, acc[0][0]);
                acc[0][1] = fmaf(av0, w.y, acc[0][1]);
                acc[0][2] = fmaf(av0, w.z, acc[0][2]);
                acc[0][3] = fmaf(av0, w.w, acc[0][3]);
                acc[1][0] = fmaf(av1, w.x, acc[1][0]);
                acc[1][1] = fmaf(av1, w.y, acc[1][1]);
                acc[1][2] = fmaf(av1, w.z, acc[1][2]);
                acc[1][3] = fmaf(av1, w.w, acc[1][3]);
            }
        }
        {   // tail k = 164
            const int k = IND - 1;
            float4 w = *reinterpret_cast<const float4*>(Ws + k * HID + cg * 4);
            float av0 = xr0[k], av1 = xr1[k];
            acc[0][0] = fmaf(av0, w.x, acc[0][0]);
            acc[0][1] = fmaf(av0, w.y, acc[0][1]);
            acc[0][2] = fmaf(av0, w.z, acc[0][2]);
            acc[0][3] = fmaf(av0, w.w, acc[0][3]);
            acc[1][0] = fmaf(av1, w.x, acc[1][0]);
            acc[1][1] = fmaf(av1, w.y, acc[1][1]);
            acc[1][2] = fmaf(av1, w.z, acc[1][2]);
            acc[1][3] = fmaf(av1, w.w, acc[1][3]);
        }
        #pragma unroll
        for (int i = 0; i < 2; i++) {
            int n = n0 + ng * 2 + i;
            if (n < Nn) {
                float4 o;
                o.x = fmaxf(acc[i][0], 0.f);
                o.y = fmaxf(acc[i][1], 0.f);
                o.z = fmaxf(acc[i][2], 0.f);
                o.w = fmaxf(acc[i][3], 0.f);
                *reinterpret_cast<float4*>(out + (size_t)n * HID + cg * 4) = o;
            }
        }
    }
}

// ====== SAGE GEMM: out = relu([aggr | h] @ [Wl ; Wr] + bl) ======
// FINAL=true fuses the classifier: res[n] = relu(row) . Wc + bc
#define AS_STRIDE 132
#define SAGE_SMEM ((128 * HID + 64 * AS_STRIDE) * 4)

template<bool FINAL>
__global__ __launch_bounds__(256) void sage_gemm(
    const float* __restrict__ h, const float* __restrict__ aggr,
    const float* __restrict__ Wl, const float* __restrict__ bl,
    const float* __restrict__ Wr, float* __restrict__ out,
    const float* __restrict__ Wc, const float* __restrict__ bc)
{
    extern __shared__ float sm[];
    float* Ws = sm;                  // [128][64]: rows 0-63 Wl, 64-127 Wr
    float* As = sm + 128 * HID;      // [64][AS_STRIDE]
    const int t = threadIdx.x;
    for (int i = t; i < HID * HID; i += 256) {
        Ws[i] = Wl[i];
        Ws[HID * HID + i] = Wr[i];
    }
    const int cg = t & 15;
    const int ng = t >> 4;           // 16 groups x 4 nodes
    float b0 = bl[cg * 4 + 0], b1 = bl[cg * 4 + 1], b2 = bl[cg * 4 + 2], b3 = bl[cg * 4 + 3];
    float4 wc = make_float4(0.f, 0.f, 0.f, 0.f);
    float bc0 = 0.f;
    if (FINAL) {
        wc = *reinterpret_cast<const float4*>(Wc + cg * 4);
        bc0 = bc[0];
    }
    const int ntiles = (Nn + 63) / 64;
    for (int tile = blockIdx.x; tile < ntiles; tile += gridDim.x) {
        const int n0 = tile * 64;
        __syncthreads();
        for (int i = t; i < 64 * 32; i += 256) {
            int node = i >> 5;
            int p = i & 31;
            int n = n0 + node;
            float4 v;
            if (n < Nn)
                v = (p < 16) ? *reinterpret_cast<const float4*>(aggr + (size_t)n * HID + p * 4)
                             : *reinterpret_cast<const float4*>(h + (size_t)n * HID + (p - 16) * 4);
            else
                v = make_float4(0.f, 0.f, 0.f, 0.f);
            *reinterpret_cast<float4*>(As + node * AS_STRIDE + p * 4) = v;
        }
        __syncthreads();
        float acc[4][4];
        #pragma unroll
        for (int i = 0; i < 4; i++) { acc[i][0] = b0; acc[i][1] = b1; acc[i][2] = b2; acc[i][3] = b3; }
        #pragma unroll 2
        for (int k4 = 0; k4 < 32; k4++) {
            float4 a[4];
            #pragma unroll
            for (int i = 0; i < 4; i++)
                a[i] = *reinterpret_cast<const float4*>(As + (ng * 4 + i) * AS_STRIDE + k4 * 4);
            #pragma unroll
            for (int kk = 0; kk < 4; kk++) {
                float4 w = *reinterpret_cast<const float4*>(Ws + (k4 * 4 + kk) * HID + cg * 4);
                #pragma unroll
                for (int i = 0; i < 4; i++) {
                    float av = (kk == 0) ? a[i].x : (kk == 1) ? a[i].y : (kk == 2) ? a[i].z : a[i].w;
                    acc[i][0] = fmaf(av, w.x, acc[i][0]);
                    acc[i][1] = fmaf(av, w.y, acc[i][1]);
                    acc[i][2] = fmaf(av, w.z, acc[i][2]);
                    acc[i][3] = fmaf(av, w.w, acc[i][3]);
                }
            }
        }
        if (FINAL) {
            float part[4];
            #pragma unroll
            for (int i = 0; i < 4; i++) {
                part[i] = fmaxf(acc[i][0], 0.f) * wc.x;
                part[i] = fmaf(fmaxf(acc[i][1], 0.f), wc.y, part[i]);
                part[i] = fmaf(fmaxf(acc[i][2], 0.f), wc.z, part[i]);
                part[i] = fmaf(fmaxf(acc[i][3], 0.f), wc.w, part[i]);
            }
            #pragma unroll
            for (int i = 0; i < 4; i++) {
                #pragma unroll
                for (int o = 1; o < 16; o <<= 1)
                    part[i] += __shfl_xor_sync(0xffffffffu, part[i], o);
            }
            if (cg == 0) {
                #pragma unroll
                for (int i = 0; i < 4; i++) {
                    int n = n0 + ng * 4 + i;
                    if (n < Nn) out[n] = part[i] + bc0;
                }
            }
        } else {
            #pragma unroll
            for (int i = 0; i < 4; i++) {
                int n = n0 + ng * 4 + i;
                if (n < Nn) {
                    float4 o;
                    o.x = fmaxf(acc[i][0], 0.f);
                    o.y = fmaxf(acc[i][1], 0.f);
                    o.z = fmaxf(acc[i][2], 0.f);
                    o.w = fmaxf(acc[i][3], 0.f);
                    *reinterpret_cast<float4*>(out + (size_t)n * HID + cg * 4) = o;
                }
            }
        }
    }
}

extern "C" void kernel_launch(void* const* d_in, const int* in_sizes, int n_in,
                              void* d_out, int out_size)
{
    const float* x   = (const float*)d_in[0];
    const int*   ei  = (const int*)d_in[1];
    const float* Wp  = (const float*)d_in[2];
    const float* bp  = (const float*)d_in[3];
    const float* W1l = (const float*)d_in[4];
    const float* b1l = (const float*)d_in[5];
    const float* W1r = (const float*)d_in[6];
    const float* W2l = (const float*)d_in[7];
    const float* b2l = (const float*)d_in[8];
    const float* W2r = (const float*)d_in[9];
    const float* Wc  = (const float*)d_in[10];
    const float* bc  = (const float*)d_in[11];
    float* out = (float*)d_out;

    const int* src = ei;
    const int* dst = ei + Ee;

    float *h0, *h1, *aggr;
    int *degi, *off, *cur, *csr, *bsum, *bscan;
    cudaGetSymbolAddress((void**)&h0, g_h0);
    cudaGetSymbolAddress((void**)&h1, g_h1);
    cudaGetSymbolAddress((void**)&aggr, g_aggr);
    cudaGetSymbolAddress((void**)&degi, g_degi);
    cudaGetSymbolAddress((void**)&off, g_off);
    cudaGetSymbolAddress((void**)&cur, g_cur);
    cudaGetSymbolAddress((void**)&csr, g_csr);
    cudaGetSymbolAddress((void**)&bsum, g_bsum);
    cudaGetSymbolAddress((void**)&bscan, g_bscan);

    static cudaStream_t s2 = nullptr;
    static cudaEvent_t evFork = nullptr, evJoin = nullptr;
    if (!s2) {
        cudaStreamCreateWithFlags(&s2, cudaStreamNonBlocking);
        cudaEventCreateWithFlags(&evFork, cudaEventDisableTiming);
        cudaEventCreateWithFlags(&evJoin, cudaEventDisableTiming);
        cudaFuncSetAttribute(proj_gemm, cudaFuncAttributeMaxDynamicSharedMemorySize, PROJ_SMEM);
        cudaFuncSetAttribute(sage_gemm<false>, cudaFuncAttributeMaxDynamicSharedMemorySize, SAGE_SMEM);
        cudaFuncSetAttribute(sage_gemm<true>, cudaFuncAttributeMaxDynamicSharedMemorySize, SAGE_SMEM);
    }

    // ---- fork: CSR build on side stream, proj on main stream ----
    cudaEventRecord(evFork, 0);
    cudaStreamWaitEvent(s2, evFork, 0);

    cudaMemsetAsync(degi, 0, Nn * sizeof(int), s2);
    deg_kernel<<<(Ee + 255) / 256, 256, 0, s2>>>(dst, degi);
    scan1<<<NB1K, 256, 0, s2>>>(degi, bsum);
    scan2<<<1, 256, 0, s2>>>(bsum, bscan);
    scan3<<<NB1K, 256, 0, s2>>>(degi, bscan, off, cur);
    place_kernel<<<(Ee + 255) / 256, 256, 0, s2>>>(src, dst, cur, csr);
    cudaEventRecord(evJoin, s2);

    proj_gemm<<<444, 256, PROJ_SMEM>>>(x, Wp, bp, h0);

    // ---- join ----
    cudaStreamWaitEvent(0, evJoin, 0);

    // ---- layer 1 ----
    gather_mean<<<(Nn * 32 + 255) / 256, 256>>>(csr, off, degi, h0, aggr);
    sage_gemm<false><<<444, 256, SAGE_SMEM>>>(h0, aggr, W1l, b1l, W1r, h1, nullptr, nullptr);

    // ---- layer 2 (+ fused classifier) ----
    gather_mean<<<(Nn * 32 + 255) / 256, 256>>>(csr, off, degi, h1, aggr);
    sage_gemm<true><<<444, 256, SAGE_SMEM>>>(h1, aggr, W2l, b2l, W2r, out, Wc, bc);
}